// round 3
// baseline (speedup 1.0000x reference)
#include <cuda_runtime.h>

#define T_LEN   2048
#define BATCH   16
#define NFREQ   1152
#define NOCT    9
#define NF0     128

typedef unsigned long long u64;

// -------- device scratch --------
__device__ float2 g_stats[BATCH];         // {inv, -mean*inv}
__device__ float  g_mag[BATCH * NFREQ];
__device__ int    g_cnt[BATCH];           // zero-init; self-resetting each launch

// -------- packed f32x2 helpers --------
__device__ __forceinline__ u64 pk(float lo, float hi) {
    u64 r; asm("mov.b64 %0,{%1,%2};" : "=l"(r) : "f"(lo), "f"(hi)); return r;
}
__device__ __forceinline__ void upk(u64 v, float& lo, float& hi) {
    asm("mov.b64 {%0,%1},%2;" : "=f"(lo), "=f"(hi) : "l"(v));
}
__device__ __forceinline__ u64 fma2(u64 a, u64 b, u64 c) {
    u64 d; asm("fma.rn.f32x2 %0,%1,%2,%3;" : "=l"(d) : "l"(a), "l"(b), "l"(c)); return d;
}
__device__ __forceinline__ u64 mul2(u64 a, u64 b) {
    u64 d; asm("mul.rn.f32x2 %0,%1,%2;" : "=l"(d) : "l"(a), "l"(b)); return d;
}
__device__ __forceinline__ u64 add2(u64 a, u64 b) {
    u64 d; asm("add.rn.f32x2 %0,%1,%2;" : "=l"(d) : "l"(a), "l"(b)); return d;
}
__device__ __forceinline__ u64 sub2(u64 a, u64 b) {
    u64 d; asm("sub.rn.f32x2 %0,%1,%2;" : "=l"(d) : "l"(a), "l"(b)); return d;
}

__device__ __forceinline__ float warp_sum(float v) {
#pragma unroll
    for (int o = 16; o; o >>= 1) v += __shfl_down_sync(0xffffffffu, v, o);
    return v;
}

// -------- kernel A: per-batch mean/std --------
__global__ __launch_bounds__(256) void stats_kernel(const float* __restrict__ batch) {
    const int b = blockIdx.x;
    const int tid = threadIdx.x;
    const float4* __restrict__ y4 = (const float4*)(batch + b * (2 * T_LEN) + T_LEN);
    __shared__ float rb[8][2];

    float s = 0.0f, q = 0.0f;
#pragma unroll
    for (int i = 0; i < 2; i++) {
        float4 v = __ldg(&y4[i * 256 + tid]);
        s += (v.x + v.y) + (v.z + v.w);
        q = fmaf(v.x, v.x, q); q = fmaf(v.y, v.y, q);
        q = fmaf(v.z, v.z, q); q = fmaf(v.w, v.w, q);
    }
    s = warp_sum(s); q = warp_sum(q);
    const int lane = tid & 31, w = tid >> 5;
    if (lane == 0) { rb[w][0] = s; rb[w][1] = q; }
    __syncthreads();
    if (tid == 0) {
        float S = 0.0f, Q = 0.0f;
#pragma unroll
        for (int i = 0; i < 8; i++) { S += rb[i][0]; Q += rb[i][1]; }
        float mean = S * (1.0f / T_LEN);
        float var  = (Q - (float)T_LEN * mean * mean) * (1.0f / (T_LEN - 1));
        float inv  = 1.0f / (sqrtf(var) + 1e-4f);
        g_stats[b] = make_float2(inv, -mean * inv);
    }
}

// eval one packed pair of time steps across 9 octaves
#define EVAL_PAIR(tv, yraw)                                                 \
    do {                                                                    \
        u64 yn = fma2((yraw), INVb, NMb);                                   \
        u64 x  = mul2((tv), W0);                                            \
        u64 qm = fma2(x, IPI, MAGC);                                        \
        u64 qf = sub2(qm, MAGC);                                            \
        u64 r  = fma2(qf, PA, x);                                           \
        r = fma2(qf, PB, r);                                                \
        u64 z = mul2(r, r);                                                 \
        u64 ps = fma2(S9c, z, S7c);                                         \
        ps = fma2(ps, z, S5c);                                              \
        ps = fma2(ps, z, S3c);                                              \
        u64 s = fma2(mul2(ps, z), r, r);                                    \
        u64 pc = fma2(C10c, z, C8c);                                        \
        pc = fma2(pc, z, C6c);                                              \
        pc = fma2(pc, z, C4c);                                              \
        pc = fma2(pc, z, C2c);                                              \
        u64 c = fma2(pc, z, ONE);                                           \
        u64 sgn = (qm & 0x0000000100000001ull) << 31;                       \
        u64 ysg = yn ^ sgn; /* doubling cancels sign for k>=1 */            \
        A1[0] = fma2(ysg, s, A1[0]);                                        \
        A2[0] = fma2(ysg, c, A2[0]);                                        \
        _Pragma("unroll")                                                   \
        for (int k = 1; k < NOCT; k++) {                                    \
            u64 u = mul2(s, s);                                             \
            u64 p = mul2(s, c);                                             \
            c = fma2(u, N2, ONE);                                           \
            s = add2(p, p);                                                 \
            A1[k] = fma2(yn, s, A1[k]);                                     \
            A2[k] = fma2(yn, c, A2[k]);                                     \
        }                                                                   \
    } while (0)

// -------- kernel B: spectral projection + fused finalize --------
// block (f0, b): 128 threads = 4 warps; warp w covers t in [w*512, w*512+512).
__global__ __launch_bounds__(128, 14) void spectral_kernel(const float* __restrict__ batch,
                                                           const float* __restrict__ freqs,
                                                           float* __restrict__ out) {
    const int f0  = blockIdx.x;
    const int b   = blockIdx.y;
    const int tid = threadIdx.x;
    const int lane = tid & 31, w = tid >> 5;

    __shared__ float sred[4][18];
    __shared__ float rstat[4][2];
    __shared__ float fmean_s, finv_s;
    __shared__ int   last_s;

    const float2 st = g_stats[b];
    const float w0f = freqs[f0] * 6.283185307179586f;

    const u64 W0   = pk(w0f, w0f);
    const u64 INVb = pk(st.x, st.x);
    const u64 NMb  = pk(st.y, st.y);
    const u64 IPI  = pk(0.3183098861837907f, 0.3183098861837907f);
    const u64 MAGC = pk(12582912.0f, 12582912.0f);
    const u64 PA   = pk(-3.140625f, -3.140625f);
    const u64 PB   = pk(-9.67502593994140625e-4f, -9.67502593994140625e-4f);
    const u64 S9c  = pk( 2.7557319223985893e-6f,  2.7557319223985893e-6f);
    const u64 S7c  = pk(-1.9841269841269841e-4f, -1.9841269841269841e-4f);
    const u64 S5c  = pk( 8.3333333333333333e-3f,  8.3333333333333333e-3f);
    const u64 S3c  = pk(-1.6666666666666666e-1f, -1.6666666666666666e-1f);
    const u64 C10c = pk(-2.7557319223985893e-7f, -2.7557319223985893e-7f);
    const u64 C8c  = pk( 2.4801587301587302e-5f,  2.4801587301587302e-5f);
    const u64 C6c  = pk(-1.3888888888888889e-3f, -1.3888888888888889e-3f);
    const u64 C4c  = pk( 4.1666666666666666e-2f,  4.1666666666666666e-2f);
    const u64 C2c  = pk(-0.5f, -0.5f);
    const u64 ONE  = pk(1.0f, 1.0f);
    const u64 N2   = pk(-2.0f, -2.0f);

    u64 A1[NOCT], A2[NOCT];
#pragma unroll
    for (int k = 0; k < NOCT; k++) { A1[k] = 0; A2[k] = 0; }

    const float4* __restrict__ ts4 = (const float4*)(batch + b * (2 * T_LEN));
    const float4* __restrict__ ys4 = (const float4*)(batch + b * (2 * T_LEN) + T_LEN);
    const int base = w * 128 + lane;

#pragma unroll
    for (int i = 0; i < 4; i++) {
        float4 t4 = __ldg(&ts4[base + i * 32]);
        float4 y4 = __ldg(&ys4[base + i * 32]);
        u64 tvA = pk(t4.x, t4.y), yA = pk(y4.x, y4.y);
        u64 tvB = pk(t4.z, t4.w), yB = pk(y4.z, y4.w);
        EVAL_PAIR(tvA, yA);
        EVAL_PAIR(tvB, yB);
    }

    // ---- per-warp packed butterfly reduction ----
#pragma unroll
    for (int k = 0; k < NOCT; k++) {
#pragma unroll
        for (int o = 16; o; o >>= 1) {
            A1[k] = add2(A1[k], __shfl_down_sync(0xffffffffu, A1[k], o));
            A2[k] = add2(A2[k], __shfl_down_sync(0xffffffffu, A2[k], o));
        }
    }
    if (lane == 0) {
#pragma unroll
        for (int k = 0; k < NOCT; k++) {
            float lo, hi;
            upk(A1[k], lo, hi); sred[w][k]        = lo + hi;
            upk(A2[k], lo, hi); sred[w][NOCT + k] = lo + hi;
        }
    }
    __syncthreads();

    // ---- combine 4 warps, write magnitude ----
    if (tid < NOCT) {
        float P1 = sred[0][tid] + sred[1][tid] + sred[2][tid] + sred[3][tid];
        float P2 = sred[0][NOCT + tid] + sred[1][NOCT + tid] +
                   sred[2][NOCT + tid] + sred[3][NOCT + tid];
        float m = sqrtf(fmaf(P1, P1, P2 * P2));
        __stcg(&g_mag[b * NFREQ + tid * NF0 + f0], m);
    }
    __threadfence();
    __syncthreads();
    if (tid == 0) last_s = (atomicAdd(&g_cnt[b], 1) == NF0 - 1);
    __syncthreads();
    if (!last_s) return;
    __threadfence();

    // ---- last block per batch: tnorm over 1152 freqs ----
    float mv[NOCT];
    float sm = 0.0f, sq = 0.0f;
#pragma unroll
    for (int j = 0; j < NOCT; j++) {
        float m = __ldcg(&g_mag[b * NFREQ + j * NF0 + tid]);
        mv[j] = m;
        sm += m;
        sq = fmaf(m, m, sq);
    }
    sm = warp_sum(sm); sq = warp_sum(sq);
    if (lane == 0) { rstat[w][0] = sm; rstat[w][1] = sq; }
    __syncthreads();
    if (tid == 0) {
        float S = rstat[0][0] + rstat[1][0] + rstat[2][0] + rstat[3][0];
        float Q = rstat[0][1] + rstat[1][1] + rstat[2][1] + rstat[3][1];
        float mean = S * (1.0f / NFREQ);
        float var  = (Q - (float)NFREQ * mean * mean) * (1.0f / (NFREQ - 1));
        fmean_s = mean;
        finv_s  = 1.0f / (sqrtf(var) + 1e-4f);
        g_cnt[b] = 0;   // reset for next graph replay
    }
    __syncthreads();
    const float mmean = fmean_s, minv = finv_s;
#pragma unroll
    for (int j = 0; j < NOCT; j++)
        out[b * NFREQ + j * NF0 + tid] = (mv[j] - mmean) * minv;
}

// -------- launch --------
extern "C" void kernel_launch(void* const* d_in, const int* in_sizes, int n_in,
                              void* d_out, int out_size) {
    const float* batch = (const float*)d_in[0];   // (16, 2, 2048) f32
    const float* freqs = (const float*)d_in[1];   // (1152,) f32
    float* out = (float*)d_out;                   // (16, 1, 1152) f32

    stats_kernel<<<BATCH, 256>>>(batch);
    spectral_kernel<<<dim3(NF0, BATCH), 128>>>(batch, freqs, out);
}

// round 5
// speedup vs baseline: 2.7015x; 2.7015x over previous
#include <cuda_runtime.h>

#define T_LEN   2048
#define BATCH   16
#define NFREQ   1152
#define NOCT    9
#define NF0     128

typedef unsigned long long u64;

// -------- device scratch --------
__device__ float2 g_stats[BATCH];         // {inv, -mean*inv}
__device__ float  g_mag[BATCH * NFREQ];
__device__ int    g_cnt[BATCH];           // zero-init; self-resetting each launch

// -------- packed f32x2 helpers --------
__device__ __forceinline__ u64 pk(float lo, float hi) {
    u64 r; asm("mov.b64 %0,{%1,%2};" : "=l"(r) : "f"(lo), "f"(hi)); return r;
}
__device__ __forceinline__ void upk(u64 v, float& lo, float& hi) {
    asm("mov.b64 {%0,%1},%2;" : "=f"(lo), "=f"(hi) : "l"(v));
}
// broadcast a compile-time float constant -> 64-bit immediate (foldable, rematerializable)
__device__ __forceinline__ u64 bc2(float v) {
    unsigned u = __float_as_uint(v);
    return (u64)u | ((u64)u << 32);
}
__device__ __forceinline__ u64 fma2(u64 a, u64 b, u64 c) {
    u64 d; asm("fma.rn.f32x2 %0,%1,%2,%3;" : "=l"(d) : "l"(a), "l"(b), "l"(c)); return d;
}
__device__ __forceinline__ u64 mul2(u64 a, u64 b) {
    u64 d; asm("mul.rn.f32x2 %0,%1,%2;" : "=l"(d) : "l"(a), "l"(b)); return d;
}
__device__ __forceinline__ u64 add2(u64 a, u64 b) {
    u64 d; asm("add.rn.f32x2 %0,%1,%2;" : "=l"(d) : "l"(a), "l"(b)); return d;
}
__device__ __forceinline__ u64 sub2(u64 a, u64 b) {
    u64 d; asm("sub.rn.f32x2 %0,%1,%2;" : "=l"(d) : "l"(a), "l"(b)); return d;
}

__device__ __forceinline__ float warp_sum(float v) {
#pragma unroll
    for (int o = 16; o; o >>= 1) v += __shfl_down_sync(0xffffffffu, v, o);
    return v;
}

// -------- kernel A: per-batch mean/std --------
__global__ __launch_bounds__(256) void stats_kernel(const float* __restrict__ batch) {
    const int b = blockIdx.x;
    const int tid = threadIdx.x;
    const float4* __restrict__ y4 = (const float4*)(batch + b * (2 * T_LEN) + T_LEN);
    __shared__ float rb[8][2];

    float s = 0.0f, q = 0.0f;
#pragma unroll
    for (int i = 0; i < 2; i++) {
        float4 v = __ldg(&y4[i * 256 + tid]);
        s += (v.x + v.y) + (v.z + v.w);
        q = fmaf(v.x, v.x, q); q = fmaf(v.y, v.y, q);
        q = fmaf(v.z, v.z, q); q = fmaf(v.w, v.w, q);
    }
    s = warp_sum(s); q = warp_sum(q);
    const int lane = tid & 31, w = tid >> 5;
    if (lane == 0) { rb[w][0] = s; rb[w][1] = q; }
    __syncthreads();
    if (tid == 0) {
        float S = 0.0f, Q = 0.0f;
#pragma unroll
        for (int i = 0; i < 8; i++) { S += rb[i][0]; Q += rb[i][1]; }
        float mean = S * (1.0f / T_LEN);
        float var  = (Q - (float)T_LEN * mean * mean) * (1.0f / (T_LEN - 1));
        float inv  = 1.0f / (sqrtf(var) + 1e-4f);
        g_stats[b] = make_float2(inv, -mean * inv);
    }
}

// one packed pair of time steps across 9 octaves
#define EVAL_PAIR(tv, yraw)                                                 \
    do {                                                                    \
        u64 x  = mul2((tv), W0);                                            \
        u64 qm = fma2(x, IPI, MAGC);                                        \
        u64 qf = sub2(qm, MAGC);                                            \
        u64 r  = fma2(qf, PA, x);                                           \
        r = fma2(qf, PB, r);                                                \
        u64 z = mul2(r, r);                                                 \
        u64 ps = fma2(S9c, z, S7c);                                         \
        ps = fma2(ps, z, S5c);                                              \
        ps = fma2(ps, z, S3c);                                              \
        u64 s = fma2(mul2(ps, z), r, r);                                    \
        u64 pc = fma2(C10c, z, C8c);                                        \
        pc = fma2(pc, z, C6c);                                              \
        pc = fma2(pc, z, C4c);                                              \
        pc = fma2(pc, z, C2c);                                              \
        u64 c = fma2(pc, z, ONE);                                           \
        u64 yn  = fma2((yraw), INVb, NMb);                                  \
        u64 ysg = yn ^ ((qm & 0x0000000100000001ull) << 31);                \
        A1[0] = fma2(ysg, s, A1[0]);                                        \
        A2[0] = fma2(ysg, c, A2[0]);                                        \
        _Pragma("unroll")                                                   \
        for (int k = 1; k < NOCT; k++) {                                    \
            u64 tc = add2(c, c);                                            \
            s = mul2(tc, s);            /* sin2 = 2c*s   */                 \
            c = fma2(tc, c, NEG1);      /* cos2 = 2c*c-1 */                 \
            A1[k] = fma2(yn, s, A1[k]);                                     \
            A2[k] = fma2(yn, c, A2[k]);                                     \
        }                                                                   \
    } while (0)

// -------- kernel B: spectral projection + fused finalize --------
// block (f0, b): 64 threads = 2 warps; each thread: 16 packed pairs.
__global__ __launch_bounds__(64) void spectral_kernel(const float* __restrict__ batch,
                                                      const float* __restrict__ freqs,
                                                      float* __restrict__ out) {
    const int f0  = blockIdx.x;
    const int b   = blockIdx.y;
    const int tid = threadIdx.x;
    const int lane = tid & 31, w = tid >> 5;

    __shared__ float sred[2][18];
    __shared__ float rstat[2][2];
    __shared__ float fmean_s, finv_s;
    __shared__ int   last_s;

    const float2 st = g_stats[b];
    const float w0f = freqs[f0] * 6.283185307179586f;

    // runtime broadcasts
    const u64 W0   = pk(w0f, w0f);
    const u64 INVb = pk(st.x, st.x);
    const u64 NMb  = pk(st.y, st.y);
    // compile-time immediates (rematerializable by ptxas)
    const u64 IPI  = bc2(0.3183098861837907f);
    const u64 MAGC = bc2(12582912.0f);
    const u64 PA   = bc2(-3.140625f);
    const u64 PB   = bc2(-9.67502593994140625e-4f);
    const u64 S9c  = bc2( 2.7557319223985893e-6f);
    const u64 S7c  = bc2(-1.9841269841269841e-4f);
    const u64 S5c  = bc2( 8.3333333333333333e-3f);
    const u64 S3c  = bc2(-1.6666666666666666e-1f);
    const u64 C10c = bc2(-2.7557319223985893e-7f);
    const u64 C8c  = bc2( 2.4801587301587302e-5f);
    const u64 C6c  = bc2(-1.3888888888888889e-3f);
    const u64 C4c  = bc2( 4.1666666666666666e-2f);
    const u64 C2c  = bc2(-0.5f);
    const u64 ONE  = bc2(1.0f);
    const u64 NEG1 = bc2(-1.0f);

    u64 A1[NOCT], A2[NOCT];
#pragma unroll
    for (int k = 0; k < NOCT; k++) { A1[k] = 0; A2[k] = 0; }

    const float4* __restrict__ ts4 = (const float4*)(batch + b * (2 * T_LEN));
    const float4* __restrict__ ys4 = (const float4*)(batch + b * (2 * T_LEN) + T_LEN);

#pragma unroll 4
    for (int i = 0; i < 8; i++) {
        float4 t4 = __ldg(&ts4[i * 64 + tid]);
        float4 y4 = __ldg(&ys4[i * 64 + tid]);
        u64 tvA = pk(t4.x, t4.y), yA = pk(y4.x, y4.y);
        u64 tvB = pk(t4.z, t4.w), yB = pk(y4.z, y4.w);
        EVAL_PAIR(tvA, yA);
        EVAL_PAIR(tvB, yB);
    }

    // ---- per-warp packed butterfly reduction (keeps lanes paired) ----
#pragma unroll
    for (int k = 0; k < NOCT; k++) {
#pragma unroll
        for (int o = 16; o; o >>= 1) {
            A1[k] = add2(A1[k], __shfl_down_sync(0xffffffffu, A1[k], o));
            A2[k] = add2(A2[k], __shfl_down_sync(0xffffffffu, A2[k], o));
        }
    }
    if (lane == 0) {
#pragma unroll
        for (int k = 0; k < NOCT; k++) {
            float lo, hi;
            upk(A1[k], lo, hi); sred[w][k]        = lo + hi;
            upk(A2[k], lo, hi); sred[w][NOCT + k] = lo + hi;
        }
    }
    __syncthreads();

    // ---- combine 2 warps, write magnitude ----
    if (tid < NOCT) {
        float P1 = sred[0][tid]        + sred[1][tid];
        float P2 = sred[0][NOCT + tid] + sred[1][NOCT + tid];
        float m = sqrtf(fmaf(P1, P1, P2 * P2));
        __stcg(&g_mag[b * NFREQ + tid * NF0 + f0], m);
    }
    __threadfence();
    __syncthreads();
    if (tid == 0) last_s = (atomicAdd(&g_cnt[b], 1) == NF0 - 1);
    __syncthreads();
    if (!last_s) return;
    __threadfence();

    // ---- last block per batch: tnorm over 1152 freqs ----
    float mv[18];
    float sm = 0.0f, sq = 0.0f;
#pragma unroll
    for (int j = 0; j < 18; j++) {
        float m = __ldcg(&g_mag[b * NFREQ + j * 64 + tid]);
        mv[j] = m;
        sm += m;
        sq = fmaf(m, m, sq);
    }
    sm = warp_sum(sm); sq = warp_sum(sq);
    if (lane == 0) { rstat[w][0] = sm; rstat[w][1] = sq; }
    __syncthreads();
    if (tid == 0) {
        float S = rstat[0][0] + rstat[1][0];
        float Q = rstat[0][1] + rstat[1][1];
        float mean = S * (1.0f / NFREQ);
        float var  = (Q - (float)NFREQ * mean * mean) * (1.0f / (NFREQ - 1));
        fmean_s = mean;
        finv_s  = 1.0f / (sqrtf(var) + 1e-4f);
        g_cnt[b] = 0;   // reset for next graph replay
    }
    __syncthreads();
    const float mmean = fmean_s, minv = finv_s;
#pragma unroll
    for (int j = 0; j < 18; j++)
        out[b * NFREQ + j * 64 + tid] = (mv[j] - mmean) * minv;
}

// -------- launch --------
extern "C" void kernel_launch(void* const* d_in, const int* in_sizes, int n_in,
                              void* d_out, int out_size) {
    const float* batch = (const float*)d_in[0];   // (16, 2, 2048) f32
    const float* freqs = (const float*)d_in[1];   // (1152,) f32
    float* out = (float*)d_out;                   // (16, 1, 1152) f32

    stats_kernel<<<BATCH, 256>>>(batch);
    spectral_kernel<<<dim3(NF0, BATCH), 64>>>(batch, freqs, out);
}